// round 11
// baseline (speedup 1.0000x reference)
#include <cuda_runtime.h>
#include <math.h>

// y[t][c] = x[t][c] + beta * y[t-1][c],  beta = sigmoid(beta_param)
// T = 1024 rows, C = 16384 columns, fp32.
//
// Halo formulation: beta^k decays fast (beta = sigmoid(2) ~ 0.881 =>
// beta^147 < 1e-8), so each segment computes its incoming state y[t0-1]
// directly from at most ~147 preceding x rows. No inter-block sync.
// R11: L 128 -> 64 (NSEG 8 -> 16): 1024 blocks, ~2x resident warps/SM.
#define T_DIM   1024
#define C_DIM   16384
#define L_DIM   64             // rows per block (segment length)
#define TPB     256            // threads per block = columns per block
#define NCB     (C_DIM/TPB)    // 64 column-blocks
#define NSEG    (T_DIM/L_DIM)  // 16 segments

__global__ __launch_bounds__(TPB)
void pli_halo_kernel(const float* __restrict__ x,
                     const float* __restrict__ beta_param,
                     float* __restrict__ y) {
    const int col = blockIdx.x * TPB + threadIdx.x;
    const int t0  = blockIdx.y * L_DIM;

    const float beta = 1.0f / (1.0f + expf(-__ldg(beta_param)));

    // Halo length: smallest k with beta^k < 1e-8, i.e. k > 18.42/(-ln beta).
    const float logb = logf(beta);
    int kneed = (logb < -1e-7f) ? (int)(18.4207f / (-logb)) + 2 : T_DIM;
    if (kneed < 0) kneed = 0;
    const int jmax = (t0 < kneed) ? t0 : kneed;

    const float*  xp = x + (size_t)t0 * C_DIM + col;
    float*        yp = y + (size_t)t0 * C_DIM + col;
    const ptrdiff_t Cs = C_DIM;

    const float b4 = (beta * beta) * (beta * beta);

    // ---- halo pass: P = y[t0-1] = sum_{j=1..jmax} beta^(j-1) * x[t0-j] ----
    float P = 0.0f;
    {
        float w = 1.0f;            // beta^(j-1) at loop head
        int j = 1;
        for (; j + 3 <= jmax; j += 4) {
            float a0 = xp[-(ptrdiff_t)(j + 0) * Cs];
            float a1 = xp[-(ptrdiff_t)(j + 1) * Cs];
            float a2 = xp[-(ptrdiff_t)(j + 2) * Cs];
            float a3 = xp[-(ptrdiff_t)(j + 3) * Cs];
            // inner = a0 + beta*a1 + beta^2*a2 + beta^3*a3
            float inner = fmaf(beta, fmaf(beta, fmaf(beta, a3, a2), a1), a0);
            P = fmaf(w, inner, P);
            w *= b4;
        }
        for (; j <= jmax; ++j) {
            P = fmaf(w, xp[-(ptrdiff_t)j * Cs], P);
            w *= beta;
        }
    }

    // ---- streaming scan: acc = y[t0-1], y[t0+k] = x[t0+k] + beta*acc ----
    float acc = P;
#pragma unroll
    for (int kk = 0; kk < L_DIM; kk += 8) {
        float v0 = xp[(ptrdiff_t)(kk + 0) * Cs];
        float v1 = xp[(ptrdiff_t)(kk + 1) * Cs];
        float v2 = xp[(ptrdiff_t)(kk + 2) * Cs];
        float v3 = xp[(ptrdiff_t)(kk + 3) * Cs];
        float v4 = xp[(ptrdiff_t)(kk + 4) * Cs];
        float v5 = xp[(ptrdiff_t)(kk + 5) * Cs];
        float v6 = xp[(ptrdiff_t)(kk + 6) * Cs];
        float v7 = xp[(ptrdiff_t)(kk + 7) * Cs];
        acc = fmaf(beta, acc, v0); yp[(ptrdiff_t)(kk + 0) * Cs] = acc;
        acc = fmaf(beta, acc, v1); yp[(ptrdiff_t)(kk + 1) * Cs] = acc;
        acc = fmaf(beta, acc, v2); yp[(ptrdiff_t)(kk + 2) * Cs] = acc;
        acc = fmaf(beta, acc, v3); yp[(ptrdiff_t)(kk + 3) * Cs] = acc;
        acc = fmaf(beta, acc, v4); yp[(ptrdiff_t)(kk + 4) * Cs] = acc;
        acc = fmaf(beta, acc, v5); yp[(ptrdiff_t)(kk + 5) * Cs] = acc;
        acc = fmaf(beta, acc, v6); yp[(ptrdiff_t)(kk + 6) * Cs] = acc;
        acc = fmaf(beta, acc, v7); yp[(ptrdiff_t)(kk + 7) * Cs] = acc;
    }
}

extern "C" void kernel_launch(void* const* d_in, const int* in_sizes, int n_in,
                              void* d_out, int out_size) {
    const float* x  = (const float*)d_in[0];
    const float* bp = (const float*)d_in[1];
    float*       y  = (float*)d_out;
    (void)in_sizes; (void)n_in; (void)out_size;

    dim3 grid(NCB, NSEG);
    pli_halo_kernel<<<grid, TPB>>>(x, bp, y);
}

// round 12
// speedup vs baseline: 1.0018x; 1.0018x over previous
#include <cuda_runtime.h>
#include <math.h>

// y[t][c] = x[t][c] + beta * y[t-1][c],  beta = sigmoid(beta_param)
// T = 1024 rows, C = 16384 columns, fp32.
//
// Halo formulation (no inter-block sync): beta^147 < 1e-8, so each segment
// computes its incoming state y[t0-1] from at most ~147 preceding x rows.
// R12: float2 per thread -> LDG.64, half the instructions, 2x bytes in
// flight per warp. Grid stays 512 blocks (NCB=32, NSEG=16).
#define T_DIM   1024
#define C_DIM   16384
#define C2      (C_DIM/2)      // 8192 float2 columns
#define L_DIM   64             // rows per block (segment length)
#define TPB     256            // threads per block (each owns one float2 col)
#define NCB     (C2/TPB)       // 32 column-blocks
#define NSEG    (T_DIM/L_DIM)  // 16 segments

__global__ __launch_bounds__(TPB)
void pli_halo_kernel(const float2* __restrict__ x,
                     const float* __restrict__ beta_param,
                     float2* __restrict__ y) {
    const int col = blockIdx.x * TPB + threadIdx.x;   // float2 column index
    const int t0  = blockIdx.y * L_DIM;

    const float beta = 1.0f / (1.0f + expf(-__ldg(beta_param)));

    // Halo length: smallest k with beta^k < 1e-8, i.e. k > 18.42/(-ln beta).
    const float logb = logf(beta);
    int kneed = (logb < -1e-7f) ? (int)(18.4207f / (-logb)) + 2 : T_DIM;
    if (kneed < 0) kneed = 0;
    const int jmax = (t0 < kneed) ? t0 : kneed;

    const float2* xp = x + (size_t)t0 * C2 + col;
    float2*       yp = y + (size_t)t0 * C2 + col;
    const ptrdiff_t Cs = C2;

    const float b4 = (beta * beta) * (beta * beta);

    // ---- halo: P = y[t0-1] = sum_{j=1..jmax} beta^(j-1) * x[t0-j] ----
    float Px = 0.0f, Py = 0.0f;
    {
        float w = 1.0f;            // beta^(j-1)
        int j = 1;
        for (; j + 3 <= jmax; j += 4) {
            float2 a0 = xp[-(ptrdiff_t)(j + 0) * Cs];
            float2 a1 = xp[-(ptrdiff_t)(j + 1) * Cs];
            float2 a2 = xp[-(ptrdiff_t)(j + 2) * Cs];
            float2 a3 = xp[-(ptrdiff_t)(j + 3) * Cs];
            // inner = a0 + b*a1 + b^2*a2 + b^3*a3  (Horner per component)
            float ix = fmaf(beta, fmaf(beta, fmaf(beta, a3.x, a2.x), a1.x), a0.x);
            float iy = fmaf(beta, fmaf(beta, fmaf(beta, a3.y, a2.y), a1.y), a0.y);
            Px = fmaf(w, ix, Px);
            Py = fmaf(w, iy, Py);
            w *= b4;
        }
        for (; j <= jmax; ++j) {
            float2 a = xp[-(ptrdiff_t)j * Cs];
            Px = fmaf(w, a.x, Px);
            Py = fmaf(w, a.y, Py);
            w *= beta;
        }
    }

    // ---- streaming scan: acc = y[t0-1]; y[k] = x[k] + beta*acc ----
    float ax = Px, ay = Py;
#pragma unroll
    for (int kk = 0; kk < L_DIM; kk += 8) {
        float2 v0 = xp[(ptrdiff_t)(kk + 0) * Cs];
        float2 v1 = xp[(ptrdiff_t)(kk + 1) * Cs];
        float2 v2 = xp[(ptrdiff_t)(kk + 2) * Cs];
        float2 v3 = xp[(ptrdiff_t)(kk + 3) * Cs];
        float2 v4 = xp[(ptrdiff_t)(kk + 4) * Cs];
        float2 v5 = xp[(ptrdiff_t)(kk + 5) * Cs];
        float2 v6 = xp[(ptrdiff_t)(kk + 6) * Cs];
        float2 v7 = xp[(ptrdiff_t)(kk + 7) * Cs];
        float2 o;
        ax = fmaf(beta, ax, v0.x); ay = fmaf(beta, ay, v0.y);
        o.x = ax; o.y = ay; __stcs(&yp[(ptrdiff_t)(kk + 0) * Cs], o);
        ax = fmaf(beta, ax, v1.x); ay = fmaf(beta, ay, v1.y);
        o.x = ax; o.y = ay; __stcs(&yp[(ptrdiff_t)(kk + 1) * Cs], o);
        ax = fmaf(beta, ax, v2.x); ay = fmaf(beta, ay, v2.y);
        o.x = ax; o.y = ay; __stcs(&yp[(ptrdiff_t)(kk + 2) * Cs], o);
        ax = fmaf(beta, ax, v3.x); ay = fmaf(beta, ay, v3.y);
        o.x = ax; o.y = ay; __stcs(&yp[(ptrdiff_t)(kk + 3) * Cs], o);
        ax = fmaf(beta, ax, v4.x); ay = fmaf(beta, ay, v4.y);
        o.x = ax; o.y = ay; __stcs(&yp[(ptrdiff_t)(kk + 4) * Cs], o);
        ax = fmaf(beta, ax, v5.x); ay = fmaf(beta, ay, v5.y);
        o.x = ax; o.y = ay; __stcs(&yp[(ptrdiff_t)(kk + 5) * Cs], o);
        ax = fmaf(beta, ax, v6.x); ay = fmaf(beta, ay, v6.y);
        o.x = ax; o.y = ay; __stcs(&yp[(ptrdiff_t)(kk + 6) * Cs], o);
        ax = fmaf(beta, ax, v7.x); ay = fmaf(beta, ay, v7.y);
        o.x = ax; o.y = ay; __stcs(&yp[(ptrdiff_t)(kk + 7) * Cs], o);
    }
}

extern "C" void kernel_launch(void* const* d_in, const int* in_sizes, int n_in,
                              void* d_out, int out_size) {
    const float2* x  = (const float2*)d_in[0];
    const float*  bp = (const float*)d_in[1];
    float2*       y  = (float2*)d_out;
    (void)in_sizes; (void)n_in; (void)out_size;

    dim3 grid(NCB, NSEG);
    pli_halo_kernel<<<grid, TPB>>>(x, bp, y);
}

// round 13
// speedup vs baseline: 1.1426x; 1.1405x over previous
#include <cuda_runtime.h>
#include <math.h>

// y[t][c] = x[t][c] + beta * y[t-1][c],  beta = sigmoid(beta_param)
// T = 1024 rows, C = 16384 columns, fp32.
//
// Halo formulation (no inter-block sync): beta^147 < 1e-8, so each segment
// computes its incoming state y[t0-1] from at most ~147 preceding x rows.
// R13: L=256 halves halo overhead (147/256 vs 147/128); TPB=128 keeps the
// proven 512-block grid; 16-deep explicit load batches + 64-reg budget
// raise MLP.
#define T_DIM   1024
#define C_DIM   16384
#define L_DIM   256            // rows per block (segment length)
#define TPB     128            // threads per block = columns per block
#define NCB     (C_DIM/TPB)    // 128 column-blocks
#define NSEG    (T_DIM/L_DIM)  // 4 segments -> grid = 512 blocks

__global__ __launch_bounds__(TPB, 8)   // 8*128 threads/SM budget -> <=64 regs
void pli_halo_kernel(const float* __restrict__ x,
                     const float* __restrict__ beta_param,
                     float* __restrict__ y) {
    const int col = blockIdx.x * TPB + threadIdx.x;
    const int t0  = blockIdx.y * L_DIM;

    const float beta = 1.0f / (1.0f + expf(-__ldg(beta_param)));

    // Halo length: smallest k with beta^k < 1e-8, i.e. k > 18.42/(-ln beta).
    const float logb = logf(beta);
    int kneed = (logb < -1e-7f) ? (int)(18.4207f / (-logb)) + 2 : T_DIM;
    if (kneed < 0) kneed = 0;
    const int jmax = (t0 < kneed) ? t0 : kneed;

    const float*  xp = x + (size_t)t0 * C_DIM + col;
    float*        yp = y + (size_t)t0 * C_DIM + col;
    const ptrdiff_t Cs = C_DIM;

    // beta^16 via 4 squarings
    float b16 = beta;
#pragma unroll
    for (int i = 0; i < 4; ++i) b16 *= b16;

    // ---- halo: P = y[t0-1] = sum_{j=1..jmax} beta^(j-1) * x[t0-j] ----
    // 16 independent loads batched before the reduction -> high MLP.
    float P = 0.0f;
    {
        float w = 1.0f;            // beta^(j-1) at loop head
        int j = 1;
        for (; j + 15 <= jmax; j += 16) {
            float a[16];
#pragma unroll
            for (int i = 0; i < 16; ++i)
                a[i] = xp[-(ptrdiff_t)(j + i) * Cs];
            // inner = a0 + b*a1 + ... + b^15*a15 (Horner, high->low)
            float inner = a[15];
#pragma unroll
            for (int i = 14; i >= 0; --i)
                inner = fmaf(beta, inner, a[i]);
            P = fmaf(w, inner, P);
            w *= b16;
        }
        for (; j <= jmax; ++j) {
            P = fmaf(w, xp[-(ptrdiff_t)j * Cs], P);
            w *= beta;
        }
    }

    // ---- streaming scan: 16 chunks of 16; loads batched ahead of the
    //      dependent fma+store chain.
    float acc = P;
#pragma unroll 2
    for (int kk = 0; kk < L_DIM; kk += 16) {
        float v[16];
#pragma unroll
        for (int i = 0; i < 16; ++i)
            v[i] = xp[(ptrdiff_t)(kk + i) * Cs];
#pragma unroll
        for (int i = 0; i < 16; ++i) {
            acc = fmaf(beta, acc, v[i]);
            yp[(ptrdiff_t)(kk + i) * Cs] = acc;
        }
    }
}

extern "C" void kernel_launch(void* const* d_in, const int* in_sizes, int n_in,
                              void* d_out, int out_size) {
    const float* x  = (const float*)d_in[0];
    const float* bp = (const float*)d_in[1];
    float*       y  = (float*)d_out;
    (void)in_sizes; (void)n_in; (void)out_size;

    dim3 grid(NCB, NSEG);
    pli_halo_kernel<<<grid, TPB>>>(x, bp, y);
}

// round 14
// speedup vs baseline: 1.1556x; 1.0114x over previous
#include <cuda_runtime.h>
#include <math.h>

// y[t][c] = x[t][c] + beta * y[t-1][c],  beta = sigmoid(beta_param)
// T = 1024 rows, C = 16384 columns, fp32.
//
// Halo formulation (no inter-block sync): beta^147 < 1e-8, so each segment
// computes its incoming state y[t0-1] from at most ~147 preceding x rows.
// R14: batch depth 32 (per-warp MLP ~32, under the ~55 HW cap) and a
// 4-accumulator halo reduction so the dependent-FMA phase never drains the
// load queue. Grid stays 512 blocks (L=256, TPB=128).
#define T_DIM   1024
#define C_DIM   16384
#define L_DIM   256            // rows per block (segment length)
#define TPB     128            // threads per block = columns per block
#define NCB     (C_DIM/TPB)    // 128 column-blocks
#define NSEG    (T_DIM/L_DIM)  // 4 segments -> grid = 512 blocks

__global__ __launch_bounds__(TPB, 4)   // allow up to ~128 regs
void pli_halo_kernel(const float* __restrict__ x,
                     const float* __restrict__ beta_param,
                     float* __restrict__ y) {
    const int col = blockIdx.x * TPB + threadIdx.x;
    const int t0  = blockIdx.y * L_DIM;

    const float beta = 1.0f / (1.0f + expf(-__ldg(beta_param)));

    // Halo length: smallest k with beta^k < 1e-8, i.e. k > 18.42/(-ln beta).
    const float logb = logf(beta);
    int kneed = (logb < -1e-7f) ? (int)(18.4207f / (-logb)) + 2 : T_DIM;
    if (kneed < 0) kneed = 0;
    const int jmax = (t0 < kneed) ? t0 : kneed;

    const float*  xp = x + (size_t)t0 * C_DIM + col;
    float*        yp = y + (size_t)t0 * C_DIM + col;
    const ptrdiff_t Cs = C_DIM;

    // beta^8, beta^16, beta^24, beta^32 for combining sub-accumulators
    float b8 = beta;
#pragma unroll
    for (int i = 0; i < 3; ++i) b8 *= b8;      // beta^8
    const float b16 = b8 * b8;
    const float b24 = b16 * b8;
    const float b32 = b16 * b16;

    // ---- halo: P = y[t0-1] = sum_{j=1..jmax} beta^(j-1) * x[t0-j] ----
    float P = 0.0f;
    {
        float w = 1.0f;            // beta^(j-1) at loop head
        int j = 1;
        for (; j + 31 <= jmax; j += 32) {
            float a[32];
#pragma unroll
            for (int i = 0; i < 32; ++i)       // 32 independent loads first
                a[i] = xp[-(ptrdiff_t)(j + i) * Cs];
            // 4 independent 8-deep Horner chains (break serial dependency)
            float A0 = a[7],  A1 = a[15], A2 = a[23], A3 = a[31];
#pragma unroll
            for (int i = 6; i >= 0; --i) {
                A0 = fmaf(beta, A0, a[i]);
                A1 = fmaf(beta, A1, a[8  + i]);
                A2 = fmaf(beta, A2, a[16 + i]);
                A3 = fmaf(beta, A3, a[24 + i]);
            }
            // inner = A0 + b^8 A1 + b^16 A2 + b^24 A3
            float inner = fmaf(b8, A1, A0);
            inner = fmaf(b16, A2, inner);
            inner = fmaf(b24, A3, inner);
            P = fmaf(w, inner, P);
            w *= b32;
        }
        for (; j <= jmax; ++j) {
            P = fmaf(w, xp[-(ptrdiff_t)j * Cs], P);
            w *= beta;
        }
    }

    // ---- streaming scan: 8 chunks of 32; loads batched ahead of the
    //      dependent fma+store chain.
    float acc = P;
    for (int kk = 0; kk < L_DIM; kk += 32) {
        float v[32];
#pragma unroll
        for (int i = 0; i < 32; ++i)
            v[i] = xp[(ptrdiff_t)(kk + i) * Cs];
#pragma unroll
        for (int i = 0; i < 32; ++i) {
            acc = fmaf(beta, acc, v[i]);
            yp[(ptrdiff_t)(kk + i) * Cs] = acc;
        }
    }
}

extern "C" void kernel_launch(void* const* d_in, const int* in_sizes, int n_in,
                              void* d_out, int out_size) {
    const float* x  = (const float*)d_in[0];
    const float* bp = (const float*)d_in[1];
    float*       y  = (float*)d_out;
    (void)in_sizes; (void)n_in; (void)out_size;

    dim3 grid(NCB, NSEG);
    pli_halo_kernel<<<grid, TPB>>>(x, bp, y);
}

// round 15
// speedup vs baseline: 1.1889x; 1.0288x over previous
#include <cuda_runtime.h>
#include <math.h>

// y[t][c] = x[t][c] + beta * y[t-1][c],  beta = sigmoid(beta_param)
// T = 1024 rows, C = 16384 columns, fp32.
//
// Halo formulation (no inter-block sync): beta^147 < 1e-8, so each segment
// computes its incoming state y[t0-1] from at most ~147 preceding x rows.
// R15: register double-buffered prefetch in halo and scan -> loads stay in
// flight during the reduce/store phases; __stcs keeps y from evicting x in L2.
#define T_DIM   1024
#define C_DIM   16384
#define L_DIM   256            // rows per block (segment length)
#define TPB     128            // threads per block = columns per block
#define NCB     (C_DIM/TPB)    // 128 column-blocks
#define NSEG    (T_DIM/L_DIM)  // 4 segments -> grid = 512 blocks
#define BD      32             // batch depth

__global__ __launch_bounds__(TPB, 4)
void pli_halo_kernel(const float* __restrict__ x,
                     const float* __restrict__ beta_param,
                     float* __restrict__ y) {
    const int col = blockIdx.x * TPB + threadIdx.x;
    const int t0  = blockIdx.y * L_DIM;

    const float beta = 1.0f / (1.0f + expf(-__ldg(beta_param)));

    // Halo length: smallest k with beta^k < 1e-8, i.e. k > 18.42/(-ln beta).
    const float logb = logf(beta);
    int kneed = (logb < -1e-7f) ? (int)(18.4207f / (-logb)) + 2 : T_DIM;
    if (kneed < 0) kneed = 0;
    const int jmax = (t0 < kneed) ? t0 : kneed;

    const float*  xp = x + (size_t)t0 * C_DIM + col;
    float*        yp = y + (size_t)t0 * C_DIM + col;
    const ptrdiff_t Cs = C_DIM;

    // powers of beta for combining sub-accumulators
    float b8 = beta;
#pragma unroll
    for (int i = 0; i < 3; ++i) b8 *= b8;      // beta^8
    const float b16 = b8 * b8;
    const float b24 = b16 * b8;
    const float b32 = b16 * b16;

    // ---- halo: P = y[t0-1] = sum_{j=1..jmax} beta^(j-1) * x[t0-j] ----
    // Double-buffered 32-deep chunks: prefetch chunk c+1 before reducing c.
    float P = 0.0f;
    {
        const int nfull = jmax / BD;           // full 32-chunks
        float w = 1.0f;                        // beta^(j-1) at chunk head
        float a[BD];
        if (nfull > 0) {
#pragma unroll
            for (int i = 0; i < BD; ++i)
                a[i] = xp[-(ptrdiff_t)(1 + i) * Cs];
        }
        for (int c = 0; c < nfull; ++c) {
            float nb[BD];
            if (c + 1 < nfull) {
                const int j0 = 1 + (c + 1) * BD;
#pragma unroll
                for (int i = 0; i < BD; ++i)   // prefetch next chunk FIRST
                    nb[i] = xp[-(ptrdiff_t)(j0 + i) * Cs];
            }
            // 4 independent 8-deep Horner chains over a[]
            float A0 = a[7],  A1 = a[15], A2 = a[23], A3 = a[31];
#pragma unroll
            for (int i = 6; i >= 0; --i) {
                A0 = fmaf(beta, A0, a[i]);
                A1 = fmaf(beta, A1, a[8  + i]);
                A2 = fmaf(beta, A2, a[16 + i]);
                A3 = fmaf(beta, A3, a[24 + i]);
            }
            float inner = fmaf(b8, A1, A0);
            inner = fmaf(b16, A2, inner);
            inner = fmaf(b24, A3, inner);
            P = fmaf(w, inner, P);
            w *= b32;
#pragma unroll
            for (int i = 0; i < BD; ++i) a[i] = nb[i];   // rename, folds away
        }
        // remainder (scalar)
        for (int j = 1 + nfull * BD; j <= jmax; ++j) {
            P = fmaf(w, xp[-(ptrdiff_t)j * Cs], P);
            w *= beta;
        }
    }

    // ---- streaming scan with prefetch: 8 chunks of 32 ----
    float acc = P;
    {
        float v[BD];
#pragma unroll
        for (int i = 0; i < BD; ++i)
            v[i] = xp[(ptrdiff_t)i * Cs];
#pragma unroll
        for (int kk = 0; kk < L_DIM; kk += BD) {
            float nv[BD];
            if (kk + BD < L_DIM) {
#pragma unroll
                for (int i = 0; i < BD; ++i)   // prefetch next chunk FIRST
                    nv[i] = xp[(ptrdiff_t)(kk + BD + i) * Cs];
            }
#pragma unroll
            for (int i = 0; i < BD; ++i) {
                acc = fmaf(beta, acc, v[i]);
                __stcs(&yp[(ptrdiff_t)(kk + i) * Cs], acc);  // stream y past L2
            }
#pragma unroll
            for (int i = 0; i < BD; ++i) v[i] = nv[i];
        }
    }
}

extern "C" void kernel_launch(void* const* d_in, const int* in_sizes, int n_in,
                              void* d_out, int out_size) {
    const float* x  = (const float*)d_in[0];
    const float* bp = (const float*)d_in[1];
    float*       y  = (float*)d_out;
    (void)in_sizes; (void)n_in; (void)out_size;

    dim3 grid(NCB, NSEG);
    pli_halo_kernel<<<grid, TPB>>>(x, bp, y);
}